// round 15
// baseline (speedup 1.0000x reference)
#include <cuda_runtime.h>
#include <cstdint>

#define Bb 64
#define Tt 512
#define Ii 128
#define Hh 1024
#define Ll 4
#define Oo 128
#define Mm (Bb * Tt)   // 32768

#define NGROUP 4       // independent batch-groups (16 b-rows each)
#define GRP_NBLK 32    // CTAs per group barrier (the j-tiles)

// packed fp32 pair FMA
#define FFMA2(d, a, b, c) \
    asm("fma.rn.f32x2 %0, %1, %2, %3;" : "=l"(d) : "l"(a), "l"(b), "l"(c))

// bf16 tensor-core mma: D(4xf32) += A(4x.b32 bf16x2) * B(2x.b32 bf16x2)
#define MMA_BF16(c, a, b) \
    asm("mma.sync.aligned.m16n8k16.row.col.f32.bf16.bf16.f32 " \
        "{%0,%1,%2,%3}, {%4,%5,%6,%7}, {%8,%9}, {%0,%1,%2,%3};" \
        : "+f"((c)[0]), "+f"((c)[1]), "+f"((c)[2]), "+f"((c)[3]) \
        : "r"((a)[0]), "r"((a)[1]), "r"((a)[2]), "r"((a)[3]), \
          "r"((b)[0]), "r"((b)[1]))

#define LDSM_X4(r, addr) \
    asm("ldmatrix.sync.aligned.m8n8.x4.shared.b16 {%0,%1,%2,%3}, [%4];" \
        : "=r"((r)[0]), "=r"((r)[1]), "=r"((r)[2]), "=r"((r)[3]) \
        : "r"(addr))

#define CVT_BF16(h, v) \
    asm("cvt.rn.bf16.f32 %0, %1;" : "=h"(h) : "f"(v))

// fp32 scratch
__device__ float g_xin[(size_t)Bb * Tt * Hh];
__device__ float g_out[(size_t)Bb * Tt * Hh];

// bf16 hi/lo planes (pre-split GEMM operands)
__device__ uint16_t g_xh[(size_t)Bb * Tt * Ii];   // input x
__device__ uint16_t g_xl[(size_t)Bb * Tt * Ii];
__device__ uint16_t g_oh[(size_t)Bb * Tt * Hh];   // layer output (scan-written)
__device__ uint16_t g_ol[(size_t)Bb * Tt * Hh];

#define W_OFF_IH0 0
#define W_OFF_IHL (Hh * Ii)
#define W_OFF_FC  (W_OFF_IHL + (Ll - 1) * Hh * Hh)
#define W_TOTAL   (W_OFF_FC + Oo * Hh)
__device__ uint16_t g_wh[W_TOTAL];
__device__ uint16_t g_wl[W_TOTAL];

// Flag-array group barrier: one flag per CTA, all flags of a group in one
// 128B line. Monotonic values (base read at kernel entry from own flag ->
// replay-safe). Release/acquire ordering replaces full threadfences.
__device__ __align__(128) unsigned g_flags[NGROUP * GRP_NBLK];

// ---------------------------------------------------------------------------
// f32 -> (hi, lo) bf16 split prep
// ---------------------------------------------------------------------------
__global__ void cvt_hilo_kernel(const float* __restrict__ src,
                                uint16_t* __restrict__ hi,
                                uint16_t* __restrict__ lo, int n)
{
    const int i = blockIdx.x * blockDim.x + threadIdx.x;
    if (i < n) {
        const float v = src[i];
        uint16_t h; CVT_BF16(h, v);
        const float r = v - __uint_as_float((uint32_t)h << 16);
        uint16_t l; CVT_BF16(l, r);
        hi[i] = h; lo[i] = l;
    }
}

// ---------------------------------------------------------------------------
// Tensor-core GEMM on pre-split bf16 hi/lo operands (3-term, ~2^-16).
// (verbatim R12-passing kernel: 256 thr, 128x128 tile, BK32, double-buffered)
// ---------------------------------------------------------------------------
#define GSTRIDE 40
#define GTILE_B (128 * GSTRIDE * 2)
#define GAH_OFF 0
#define GAL_OFF (2 * GTILE_B)
#define GWH_OFF (4 * GTILE_B)
#define GWL_OFF (6 * GTILE_B)
#define GEMM_SMEM (8 * GTILE_B)

__global__ __launch_bounds__(256, 1) void gemm_bias_kernel(
    const uint16_t* __restrict__ Ah, const uint16_t* __restrict__ Al,
    const uint16_t* __restrict__ Wh, const uint16_t* __restrict__ Wl,
    const float* __restrict__ b1, const float* __restrict__ b2,
    float* __restrict__ C, int M, int N, int K)
{
    extern __shared__ __align__(16) char gsm[];
    uint16_t* sm16 = (uint16_t*)gsm;
    const uint32_t sbase = (uint32_t)__cvta_generic_to_shared(gsm);

    const int bm = blockIdx.x * 128;
    const int bn = blockIdx.y * 128;
    const int tid = threadIdx.x;
    const int wid = tid >> 5;
    const int lane = tid & 31;
    const int warpM = (wid >> 2) * 64;
    const int warpN = (wid & 3) * 32;
    const int lrowA = lane & 15;
    const int lcol8 = (lane >> 4) * 8;
    const int bnrow = lane >> 2;
    const int bk2   = (lane & 3) * 2;

    const int lrow  = tid >> 1;
    const int lhalf = tid & 1;
    const uint16_t* aph = Ah + (size_t)(bm + lrow) * K + lhalf * 16;
    const uint16_t* apl = Al + (size_t)(bm + lrow) * K + lhalf * 16;
    const uint16_t* wph = Wh + (size_t)(bn + lrow) * K + lhalf * 16;
    const uint16_t* wpl = Wl + (size_t)(bn + lrow) * K + lhalf * 16;
    const int sidx = lrow * GSTRIDE + lhalf * 16;

    float c[4][4][4];
#pragma unroll
    for (int mt = 0; mt < 4; mt++)
#pragma unroll
        for (int nt = 0; nt < 4; nt++)
#pragma unroll
            for (int i = 0; i < 4; i++) c[mt][nt][i] = 0.f;

    uint4 rah[2], ral[2], rwh[2], rwl[2];
#pragma unroll
    for (int q = 0; q < 2; q++) {
        rah[q] = *(const uint4*)(aph + q * 8);
        ral[q] = *(const uint4*)(apl + q * 8);
        rwh[q] = *(const uint4*)(wph + q * 8);
        rwl[q] = *(const uint4*)(wpl + q * 8);
    }
#pragma unroll
    for (int q = 0; q < 2; q++) {
        *(uint4*)&sm16[(GAH_OFF >> 1) + sidx + q * 8] = rah[q];
        *(uint4*)&sm16[(GAL_OFF >> 1) + sidx + q * 8] = ral[q];
        *(uint4*)&sm16[(GWH_OFF >> 1) + sidx + q * 8] = rwh[q];
        *(uint4*)&sm16[(GWL_OFF >> 1) + sidx + q * 8] = rwl[q];
    }
    __syncthreads();

    const int nkb = K / 32;
    int cur = 0;
    for (int kb = 0; kb < nkb; kb++) {
        if (kb + 1 < nkb) {
            const int k = (kb + 1) * 32;
#pragma unroll
            for (int q = 0; q < 2; q++) {
                rah[q] = *(const uint4*)(aph + k + q * 8);
                ral[q] = *(const uint4*)(apl + k + q * 8);
                rwh[q] = *(const uint4*)(wph + k + q * 8);
                rwl[q] = *(const uint4*)(wpl + k + q * 8);
            }
        }

        const uint32_t ah_b = sbase + GAH_OFF + cur * GTILE_B;
        const uint32_t al_b = sbase + GAL_OFF + cur * GTILE_B;
        const int wh_e = ((GWH_OFF + cur * GTILE_B) >> 1);
        const int wl_e = ((GWL_OFF + cur * GTILE_B) >> 1);

#pragma unroll
        for (int k16 = 0; k16 < 2; k16++) {
            const int koff = k16 * 16;
            uint32_t ah[4][4], al[4][4];
#pragma unroll
            for (int mt = 0; mt < 4; mt++) {
                const uint32_t ro =
                    ((warpM + mt * 16 + lrowA) * GSTRIDE + koff + lcol8) * 2;
                LDSM_X4(ah[mt], ah_b + ro);
                LDSM_X4(al[mt], al_b + ro);
            }
            uint32_t bh[4][2], bl[4][2];
#pragma unroll
            for (int nt = 0; nt < 4; nt++) {
                const int idx =
                    (warpN + nt * 8 + bnrow) * GSTRIDE + koff + bk2;
                bh[nt][0] = *(const uint32_t*)&sm16[wh_e + idx];
                bh[nt][1] = *(const uint32_t*)&sm16[wh_e + idx + 8];
                bl[nt][0] = *(const uint32_t*)&sm16[wl_e + idx];
                bl[nt][1] = *(const uint32_t*)&sm16[wl_e + idx + 8];
            }
#pragma unroll
            for (int mt = 0; mt < 4; mt++)
#pragma unroll
                for (int nt = 0; nt < 4; nt++) {
                    MMA_BF16(c[mt][nt], ah[mt], bh[nt]);
                    MMA_BF16(c[mt][nt], ah[mt], bl[nt]);
                    MMA_BF16(c[mt][nt], al[mt], bh[nt]);
                }
        }

        if (kb + 1 < nkb) {
            const int nxt = cur ^ 1;
            const int ah_e = ((GAH_OFF + nxt * GTILE_B) >> 1);
            const int al_e = ((GAL_OFF + nxt * GTILE_B) >> 1);
            const int wh_e2 = ((GWH_OFF + nxt * GTILE_B) >> 1);
            const int wl_e2 = ((GWL_OFF + nxt * GTILE_B) >> 1);
#pragma unroll
            for (int q = 0; q < 2; q++) {
                *(uint4*)&sm16[ah_e + sidx + q * 8] = rah[q];
                *(uint4*)&sm16[al_e + sidx + q * 8] = ral[q];
                *(uint4*)&sm16[wh_e2 + sidx + q * 8] = rwh[q];
                *(uint4*)&sm16[wl_e2 + sidx + q * 8] = rwl[q];
            }
            __syncthreads();
            cur = nxt;
        }
    }

#pragma unroll
    for (int nt = 0; nt < 4; nt++) {
        const int col = bn + warpN + nt * 8 + bk2;
        float bx = b1[col], by = b1[col + 1];
        if (b2 != nullptr) { bx += b2[col]; by += b2[col + 1]; }
#pragma unroll
        for (int mt = 0; mt < 4; mt++) {
            const int row = bm + warpM + mt * 16 + (lane >> 2);
            float2 s0 = make_float2(c[mt][nt][0] + bx, c[mt][nt][1] + by);
            float2 s1 = make_float2(c[mt][nt][2] + bx, c[mt][nt][3] + by);
            *(float2*)&C[(size_t)row * N + col] = s0;
            *(float2*)&C[(size_t)(row + 8) * N + col] = s1;
        }
    }
}

// ---------------------------------------------------------------------------
// Persistent FFMA2 scan, W-IN-REGISTERS + bf16 hi/lo emission.
//   g_out[b,t,j] = relu(g_xin[b,t,j] + sum_k h_prev[b,k] * Whh[j,k])
// R14 changes vs R12:
//  * flag-array barrier with st.release/ld.acquire (no threadfence, no atomic)
//  * g_xin prefetched at step start (LDG latency hidden under compute)
// ---------------------------------------------------------------------------
#define HS_WORDS (16 * 544)
#define RS_FLOATS (256 * 33)
#define SCAN_SMEM (HS_WORDS * 8 + RS_FLOATS * 4)  // 103424 B

__global__ __launch_bounds__(256, 1) void rnn_scan_kernel(
    const float* __restrict__ Whh, const float* __restrict__ hid,
    float* __restrict__ hn)
{
    extern __shared__ __align__(16) char smraw[];
    unsigned long long* Hs = (unsigned long long*)smraw;
    float* Rs = (float*)(smraw + HS_WORDS * 8);
    __shared__ unsigned s_base;

    const int jb  = blockIdx.x * 32;
    const int grp = blockIdx.y;
    const int bb  = grp * 16;
    const int tid = threadIdx.x;
    const int jg  = tid >> 5;
    const int kc  = tid & 31;

    unsigned* myflag = &g_flags[grp * GRP_NBLK + blockIdx.x];
    if (tid == 0) s_base = *myflag;   // all group flags equal at entry

    unsigned long long w[4][16];
#pragma unroll
    for (int jj = 0; jj < 4; jj++) {
        const float* wr = Whh + (size_t)(jb + jg * 4 + jj) * Hh + kc * 32;
#pragma unroll
        for (int p = 0; p < 16; p++)
            w[jj][p] = *(const unsigned long long*)(wr + p * 2);
    }
    __syncthreads();
    const unsigned base = s_base;

    // this thread's two output coordinates (fixed across t)
    const int bl0 = tid >> 5;            // 0..7  (phase 0 row)
    const int jo  = tid & 31;
    const size_t orow0 = (size_t)(bb + bl0) * Tt;        // phase 0
    const size_t orow1 = (size_t)(bb + 8 + bl0) * Tt;    // phase 1

    for (int t = 0; t < Tt; t++) {
        const float* hsrc;
        size_t bstride;
        if (t == 0) { hsrc = hid + (size_t)bb * Hh;                    bstride = Hh; }
        else        { hsrc = g_out + ((size_t)bb * Tt + (t - 1)) * Hh; bstride = (size_t)Tt * Hh; }

        // prefetch xin for both phases (consumed after compute)
        const size_t gi0 = (orow0 + t) * Hh + jb + jo;
        const size_t gi1 = (orow1 + t) * Hh + jb + jo;
        const float xpre0 = g_xin[gi0];
        const float xpre1 = g_xin[gi1];

#pragma unroll
        for (int it = 0; it < 32; it++) {
            const int fid = it * 256 + tid;
            const int b  = fid >> 9;
            const int P  = fid & 511;
            unsigned long long v =
                *(const unsigned long long*)(hsrc + (size_t)b * bstride + P * 2);
            Hs[b * 544 + (P & 15) * 33 + (P >> 4)] = v;
        }
        __syncthreads();

#pragma unroll
        for (int ph = 0; ph < 2; ph++) {
            unsigned long long acc[8][4];
#pragma unroll
            for (int i = 0; i < 8; i++)
#pragma unroll
                for (int j = 0; j < 4; j++) acc[i][j] = 0ULL;

#pragma unroll
            for (int b8 = 0; b8 < 8; b8++) {
                const unsigned long long* hrow = Hs + (ph * 8 + b8) * 544 + kc;
#pragma unroll
                for (int p = 0; p < 16; p++) {
                    const unsigned long long h2 = hrow[p * 33];
                    FFMA2(acc[b8][0], h2, w[0][p], acc[b8][0]);
                    FFMA2(acc[b8][1], h2, w[1][p], acc[b8][1]);
                    FFMA2(acc[b8][2], h2, w[2][p], acc[b8][2]);
                    FFMA2(acc[b8][3], h2, w[3][p], acc[b8][3]);
                }
            }

            __syncthreads();   // ph=1: previous reduce-read must finish
#pragma unroll
            for (int b8 = 0; b8 < 8; b8++)
#pragma unroll
                for (int jj = 0; jj < 4; jj++) {
                    float2 pa = *(float2*)&acc[b8][jj];
                    const int o = b8 * 32 + jg * 4 + jj;
                    Rs[o * 33 + kc] = pa.x + pa.y;
                }
            __syncthreads();

            {
                const float* rp = Rs + tid * 33;
                float s0 = 0.f, s1 = 0.f, s2 = 0.f, s3 = 0.f;
#pragma unroll
                for (int i = 0; i < 32; i += 4) {
                    s0 += rp[i + 0]; s1 += rp[i + 1];
                    s2 += rp[i + 2]; s3 += rp[i + 3];
                }
                const float sum = (s0 + s1) + (s2 + s3);

                const size_t base_i = (ph == 0) ? gi0 : gi1;
                const float xin = (ph == 0) ? xpre0 : xpre1;
                const float v = fmaxf(sum + xin, 0.f);
                g_out[base_i] = v;

                uint16_t hv; CVT_BF16(hv, v);
                const float rres = v - __uint_as_float((uint32_t)hv << 16);
                uint16_t lv; CVT_BF16(lv, rres);
                g_oh[base_i] = hv;
                g_ol[base_i] = lv;

                if (t == Tt - 1)
                    hn[(size_t)(bb + ph * 8 + bl0) * Hh + jb + jo] = v;
            }
        }

        // ---- release/acquire flag barrier ----
        __syncthreads();
        if (tid == 0) {
            const unsigned tgt = base + (unsigned)(t + 1);
            asm volatile("st.release.gpu.u32 [%0], %1;"
                         :: "l"(myflag), "r"(tgt) : "memory");
            const unsigned* gf = &g_flags[grp * GRP_NBLK];
            const long long t0 = clock64();
            for (;;) {
                int ok = 1;
#pragma unroll
                for (int i = 0; i < GRP_NBLK; i++) {
                    unsigned v;
                    asm volatile("ld.acquire.gpu.u32 %0, [%1];"
                                 : "=r"(v) : "l"(gf + i));
                    ok &= ((int)(v - tgt) >= 0);
                }
                if (ok) break;
                if (clock64() - t0 > 40000000LL) break;   // escape hatch
            }
        }
        __syncthreads();
    }
}

// ---------------------------------------------------------------------------
extern "C" void kernel_launch(void* const* d_in, const int* in_sizes, int n_in,
                              void* d_out, int out_size)
{
    const float* x      = (const float*)d_in[0];
    const float* hidden = (const float*)d_in[1];
    const float* Wih0   = (const float*)d_in[2];
    const float* Whh0   = (const float*)d_in[3];
    const float* bih0   = (const float*)d_in[4];
    const float* bhh0   = (const float*)d_in[5];
    const float* WihL   = (const float*)d_in[6];
    const float* WhhL   = (const float*)d_in[7];
    const float* bihL   = (const float*)d_in[8];
    const float* bhhL   = (const float*)d_in[9];
    const float* Wfc    = (const float*)d_in[10];
    const float* bfc    = (const float*)d_in[11];
    float* out = (float*)d_out;

    float* xin_p = nullptr;
    uint16_t *xh_p, *xl_p, *oh_p, *ol_p, *wh_p, *wl_p;
    cudaGetSymbolAddress((void**)&xin_p, g_xin);
    cudaGetSymbolAddress((void**)&xh_p, g_xh);
    cudaGetSymbolAddress((void**)&xl_p, g_xl);
    cudaGetSymbolAddress((void**)&oh_p, g_oh);
    cudaGetSymbolAddress((void**)&ol_p, g_ol);
    cudaGetSymbolAddress((void**)&wh_p, g_wh);
    cudaGetSymbolAddress((void**)&wl_p, g_wl);

    cudaFuncSetAttribute(rnn_scan_kernel,
                         cudaFuncAttributeMaxDynamicSharedMemorySize, SCAN_SMEM);
    cudaFuncSetAttribute(gemm_bias_kernel,
                         cudaFuncAttributeMaxDynamicSharedMemorySize, GEMM_SMEM);

    // prep: split x and GEMM weights into bf16 hi/lo (Whh stays f32 for scan)
    cvt_hilo_kernel<<<(Bb * Tt * Ii + 255) / 256, 256>>>(
        x, xh_p, xl_p, Bb * Tt * Ii);
    cvt_hilo_kernel<<<(Hh * Ii + 255) / 256, 256>>>(
        Wih0, wh_p + W_OFF_IH0, wl_p + W_OFF_IH0, Hh * Ii);
    cvt_hilo_kernel<<<((Ll - 1) * Hh * Hh + 255) / 256, 256>>>(
        WihL, wh_p + W_OFF_IHL, wl_p + W_OFF_IHL, (Ll - 1) * Hh * Hh);
    cvt_hilo_kernel<<<(Oo * Hh + 255) / 256, 256>>>(
        Wfc, wh_p + W_OFF_FC, wl_p + W_OFF_FC, Oo * Hh);

    const dim3 projGrid(Mm / 128, Hh / 128);   // 256 x 8
    const dim3 scanGrid(Hh / 32, NGROUP);      // 32 x 4 = 128 CTAs (1/SM)
    float* hn_base = out + (size_t)Bb * Tt * Oo;

    for (int l = 0; l < Ll; l++) {
        const float *Whh, *bi, *bh;
        if (l == 0) { Whh = Whh0; bi = bih0; bh = bhh0; }
        else {
            Whh = WhhL + (size_t)(l - 1) * Hh * Hh;
            bi  = bihL + (size_t)(l - 1) * Hh;
            bh  = bhhL + (size_t)(l - 1) * Hh;
        }

        // time-parallel input projection: g_xin = in @ Wih^T + b_ih + b_hh
        if (l == 0)
            gemm_bias_kernel<<<projGrid, 256, GEMM_SMEM>>>(
                xh_p, xl_p, wh_p + W_OFF_IH0, wl_p + W_OFF_IH0,
                bi, bh, xin_p, Mm, Hh, Ii);
        else
            gemm_bias_kernel<<<projGrid, 256, GEMM_SMEM>>>(
                oh_p, ol_p,
                wh_p + W_OFF_IHL + (size_t)(l - 1) * Hh * Hh,
                wl_p + W_OFF_IHL + (size_t)(l - 1) * Hh * Hh,
                bi, bh, xin_p, Mm, Hh, Hh);

        // persistent FFMA2 scan: all 512 steps in one launch
        rnn_scan_kernel<<<scanGrid, 256, SCAN_SMEM>>>(
            Whh, hidden + (size_t)l * Bb * Hh, hn_base + (size_t)l * Bb * Hh);
    }

    // output projection: out = h_last @ W_fc^T + b_fc
    gemm_bias_kernel<<<dim3(Mm / 128, Oo / 128), 256, GEMM_SMEM>>>(
        oh_p, ol_p, wh_p + W_OFF_FC, wl_p + W_OFF_FC,
        bfc, nullptr, out, Mm, Oo, Hh);
}

// round 16
// speedup vs baseline: 1.7040x; 1.7040x over previous
#include <cuda_runtime.h>
#include <cstdint>

#define Bb 64
#define Tt 512
#define Ii 128
#define Hh 1024
#define Ll 4
#define Oo 128
#define Mm (Bb * Tt)   // 32768

#define NGROUP 4       // independent batch-groups (16 b-rows each)
#define GRP_NBLK 32    // CTAs per group barrier (the j-tiles)

// packed fp32 pair FMA
#define FFMA2(d, a, b, c) \
    asm("fma.rn.f32x2 %0, %1, %2, %3;" : "=l"(d) : "l"(a), "l"(b), "l"(c))

// bf16 tensor-core mma: D(4xf32) += A(4x.b32 bf16x2) * B(2x.b32 bf16x2)
#define MMA_BF16(c, a, b) \
    asm("mma.sync.aligned.m16n8k16.row.col.f32.bf16.bf16.f32 " \
        "{%0,%1,%2,%3}, {%4,%5,%6,%7}, {%8,%9}, {%0,%1,%2,%3};" \
        : "+f"((c)[0]), "+f"((c)[1]), "+f"((c)[2]), "+f"((c)[3]) \
        : "r"((a)[0]), "r"((a)[1]), "r"((a)[2]), "r"((a)[3]), \
          "r"((b)[0]), "r"((b)[1]))

#define LDSM_X4(r, addr) \
    asm("ldmatrix.sync.aligned.m8n8.x4.shared.b16 {%0,%1,%2,%3}, [%4];" \
        : "=r"((r)[0]), "=r"((r)[1]), "=r"((r)[2]), "=r"((r)[3]) \
        : "r"(addr))

#define CVT_BF16(h, v) \
    asm("cvt.rn.bf16.f32 %0, %1;" : "=h"(h) : "f"(v))

// fp32 scratch
__device__ float g_xin[(size_t)Bb * Tt * Hh];
__device__ float g_out[(size_t)Bb * Tt * Hh];

// bf16 hi/lo planes (pre-split GEMM operands)
__device__ uint16_t g_xh[(size_t)Bb * Tt * Ii];   // input x
__device__ uint16_t g_xl[(size_t)Bb * Tt * Ii];
__device__ uint16_t g_oh[(size_t)Bb * Tt * Hh];   // layer output (scan-written)
__device__ uint16_t g_ol[(size_t)Bb * Tt * Hh];

#define W_OFF_IH0 0
#define W_OFF_IHL (Hh * Ii)
#define W_OFF_FC  (W_OFF_IHL + (Ll - 1) * Hh * Hh)
#define W_TOTAL   (W_OFF_FC + Oo * Hh)
__device__ uint16_t g_wh[W_TOTAL];
__device__ uint16_t g_wl[W_TOTAL];

// Per-group software barrier — R12-proven form: single atomic counter +
// single volatile phase word per group. Monotonic phase compared against a
// locally captured snapshot -> replay-safe. Spin bounded by clock64.
__device__ unsigned g_bar_count[NGROUP];
__device__ volatile unsigned g_bar_phase[NGROUP];

__device__ __forceinline__ void group_barrier(int g)
{
    __threadfence();
    __syncthreads();
    if (threadIdx.x == 0) {
        const unsigned old = g_bar_phase[g];
        if (atomicAdd(&g_bar_count[g], 1u) == GRP_NBLK - 1) {
            g_bar_count[g] = 0;
            __threadfence();
            g_bar_phase[g] = old + 1;
        } else {
            const long long t0 = clock64();
            while (g_bar_phase[g] == old) {
                if (clock64() - t0 > 40000000LL) break;   // escape hatch
            }
        }
        __threadfence();
    }
    __syncthreads();
}

// ---------------------------------------------------------------------------
// f32 -> (hi, lo) bf16 split prep
// ---------------------------------------------------------------------------
__global__ void cvt_hilo_kernel(const float* __restrict__ src,
                                uint16_t* __restrict__ hi,
                                uint16_t* __restrict__ lo, int n)
{
    const int i = blockIdx.x * blockDim.x + threadIdx.x;
    if (i < n) {
        const float v = src[i];
        uint16_t h; CVT_BF16(h, v);
        const float r = v - __uint_as_float((uint32_t)h << 16);
        uint16_t l; CVT_BF16(l, r);
        hi[i] = h; lo[i] = l;
    }
}

// ---------------------------------------------------------------------------
// Tensor-core GEMM on pre-split bf16 hi/lo operands (3-term, ~2^-16).
// (verbatim R12-passing kernel: 256 thr, 128x128 tile, BK32, double-buffered)
// ---------------------------------------------------------------------------
#define GSTRIDE 40
#define GTILE_B (128 * GSTRIDE * 2)
#define GAH_OFF 0
#define GAL_OFF (2 * GTILE_B)
#define GWH_OFF (4 * GTILE_B)
#define GWL_OFF (6 * GTILE_B)
#define GEMM_SMEM (8 * GTILE_B)

__global__ __launch_bounds__(256, 1) void gemm_bias_kernel(
    const uint16_t* __restrict__ Ah, const uint16_t* __restrict__ Al,
    const uint16_t* __restrict__ Wh, const uint16_t* __restrict__ Wl,
    const float* __restrict__ b1, const float* __restrict__ b2,
    float* __restrict__ C, int M, int N, int K)
{
    extern __shared__ __align__(16) char gsm[];
    uint16_t* sm16 = (uint16_t*)gsm;
    const uint32_t sbase = (uint32_t)__cvta_generic_to_shared(gsm);

    const int bm = blockIdx.x * 128;
    const int bn = blockIdx.y * 128;
    const int tid = threadIdx.x;
    const int wid = tid >> 5;
    const int lane = tid & 31;
    const int warpM = (wid >> 2) * 64;
    const int warpN = (wid & 3) * 32;
    const int lrowA = lane & 15;
    const int lcol8 = (lane >> 4) * 8;
    const int bnrow = lane >> 2;
    const int bk2   = (lane & 3) * 2;

    const int lrow  = tid >> 1;
    const int lhalf = tid & 1;
    const uint16_t* aph = Ah + (size_t)(bm + lrow) * K + lhalf * 16;
    const uint16_t* apl = Al + (size_t)(bm + lrow) * K + lhalf * 16;
    const uint16_t* wph = Wh + (size_t)(bn + lrow) * K + lhalf * 16;
    const uint16_t* wpl = Wl + (size_t)(bn + lrow) * K + lhalf * 16;
    const int sidx = lrow * GSTRIDE + lhalf * 16;

    float c[4][4][4];
#pragma unroll
    for (int mt = 0; mt < 4; mt++)
#pragma unroll
        for (int nt = 0; nt < 4; nt++)
#pragma unroll
            for (int i = 0; i < 4; i++) c[mt][nt][i] = 0.f;

    uint4 rah[2], ral[2], rwh[2], rwl[2];
#pragma unroll
    for (int q = 0; q < 2; q++) {
        rah[q] = *(const uint4*)(aph + q * 8);
        ral[q] = *(const uint4*)(apl + q * 8);
        rwh[q] = *(const uint4*)(wph + q * 8);
        rwl[q] = *(const uint4*)(wpl + q * 8);
    }
#pragma unroll
    for (int q = 0; q < 2; q++) {
        *(uint4*)&sm16[(GAH_OFF >> 1) + sidx + q * 8] = rah[q];
        *(uint4*)&sm16[(GAL_OFF >> 1) + sidx + q * 8] = ral[q];
        *(uint4*)&sm16[(GWH_OFF >> 1) + sidx + q * 8] = rwh[q];
        *(uint4*)&sm16[(GWL_OFF >> 1) + sidx + q * 8] = rwl[q];
    }
    __syncthreads();

    const int nkb = K / 32;
    int cur = 0;
    for (int kb = 0; kb < nkb; kb++) {
        if (kb + 1 < nkb) {
            const int k = (kb + 1) * 32;
#pragma unroll
            for (int q = 0; q < 2; q++) {
                rah[q] = *(const uint4*)(aph + k + q * 8);
                ral[q] = *(const uint4*)(apl + k + q * 8);
                rwh[q] = *(const uint4*)(wph + k + q * 8);
                rwl[q] = *(const uint4*)(wpl + k + q * 8);
            }
        }

        const uint32_t ah_b = sbase + GAH_OFF + cur * GTILE_B;
        const uint32_t al_b = sbase + GAL_OFF + cur * GTILE_B;
        const int wh_e = ((GWH_OFF + cur * GTILE_B) >> 1);
        const int wl_e = ((GWL_OFF + cur * GTILE_B) >> 1);

#pragma unroll
        for (int k16 = 0; k16 < 2; k16++) {
            const int koff = k16 * 16;
            uint32_t ah[4][4], al[4][4];
#pragma unroll
            for (int mt = 0; mt < 4; mt++) {
                const uint32_t ro =
                    ((warpM + mt * 16 + lrowA) * GSTRIDE + koff + lcol8) * 2;
                LDSM_X4(ah[mt], ah_b + ro);
                LDSM_X4(al[mt], al_b + ro);
            }
            uint32_t bh[4][2], bl[4][2];
#pragma unroll
            for (int nt = 0; nt < 4; nt++) {
                const int idx =
                    (warpN + nt * 8 + bnrow) * GSTRIDE + koff + bk2;
                bh[nt][0] = *(const uint32_t*)&sm16[wh_e + idx];
                bh[nt][1] = *(const uint32_t*)&sm16[wh_e + idx + 8];
                bl[nt][0] = *(const uint32_t*)&sm16[wl_e + idx];
                bl[nt][1] = *(const uint32_t*)&sm16[wl_e + idx + 8];
            }
#pragma unroll
            for (int mt = 0; mt < 4; mt++)
#pragma unroll
                for (int nt = 0; nt < 4; nt++) {
                    MMA_BF16(c[mt][nt], ah[mt], bh[nt]);
                    MMA_BF16(c[mt][nt], ah[mt], bl[nt]);
                    MMA_BF16(c[mt][nt], al[mt], bh[nt]);
                }
        }

        if (kb + 1 < nkb) {
            const int nxt = cur ^ 1;
            const int ah_e = ((GAH_OFF + nxt * GTILE_B) >> 1);
            const int al_e = ((GAL_OFF + nxt * GTILE_B) >> 1);
            const int wh_e2 = ((GWH_OFF + nxt * GTILE_B) >> 1);
            const int wl_e2 = ((GWL_OFF + nxt * GTILE_B) >> 1);
#pragma unroll
            for (int q = 0; q < 2; q++) {
                *(uint4*)&sm16[ah_e + sidx + q * 8] = rah[q];
                *(uint4*)&sm16[al_e + sidx + q * 8] = ral[q];
                *(uint4*)&sm16[wh_e2 + sidx + q * 8] = rwh[q];
                *(uint4*)&sm16[wl_e2 + sidx + q * 8] = rwl[q];
            }
            __syncthreads();
            cur = nxt;
        }
    }

#pragma unroll
    for (int nt = 0; nt < 4; nt++) {
        const int col = bn + warpN + nt * 8 + bk2;
        float bx = b1[col], by = b1[col + 1];
        if (b2 != nullptr) { bx += b2[col]; by += b2[col + 1]; }
#pragma unroll
        for (int mt = 0; mt < 4; mt++) {
            const int row = bm + warpM + mt * 16 + (lane >> 2);
            float2 s0 = make_float2(c[mt][nt][0] + bx, c[mt][nt][1] + by);
            float2 s1 = make_float2(c[mt][nt][2] + bx, c[mt][nt][3] + by);
            *(float2*)&C[(size_t)row * N + col] = s0;
            *(float2*)&C[(size_t)(row + 8) * N + col] = s1;
        }
    }
}

// ---------------------------------------------------------------------------
// Persistent FFMA2 scan, W-IN-REGISTERS + bf16 hi/lo emission.
//   g_out[b,t,j] = relu(g_xin[b,t,j] + sum_k h_prev[b,k] * Whh[j,k])
// vs R12: R12 atomic barrier restored; xin prefetched at step start;
// double-buffered Rs (Rs0/Rs1) drops two syncthreads per step (the grid
// barrier already orders prior-step Rs reads).
// ---------------------------------------------------------------------------
#define HS_WORDS (16 * 544)                        // 8B words (69632 B)
#define RS_FLOATS (256 * 33)                       // one buffer (33792 B)
#define SCAN_SMEM (HS_WORDS * 8 + 2 * RS_FLOATS * 4)  // 137216 B

__global__ __launch_bounds__(256, 1) void rnn_scan_kernel(
    const float* __restrict__ Whh, const float* __restrict__ hid,
    float* __restrict__ hn)
{
    extern __shared__ __align__(16) char smraw[];
    unsigned long long* Hs = (unsigned long long*)smraw;
    float* Rs0 = (float*)(smraw + HS_WORDS * 8);
    float* Rs1 = Rs0 + RS_FLOATS;

    const int jb  = blockIdx.x * 32;
    const int grp = blockIdx.y;
    const int bb  = grp * 16;
    const int tid = threadIdx.x;
    const int jg  = tid >> 5;
    const int kc  = tid & 31;

    unsigned long long w[4][16];
#pragma unroll
    for (int jj = 0; jj < 4; jj++) {
        const float* wr = Whh + (size_t)(jb + jg * 4 + jj) * Hh + kc * 32;
#pragma unroll
        for (int p = 0; p < 16; p++)
            w[jj][p] = *(const unsigned long long*)(wr + p * 2);
    }

    // this thread's two output coordinates (fixed across t)
    const int bl0 = tid >> 5;            // 0..7
    const int jo  = tid & 31;
    const size_t orow0 = (size_t)(bb + bl0) * Tt;        // phase 0 row
    const size_t orow1 = (size_t)(bb + 8 + bl0) * Tt;    // phase 1 row

    for (int t = 0; t < Tt; t++) {
        const float* hsrc;
        size_t bstride;
        if (t == 0) { hsrc = hid + (size_t)bb * Hh;                    bstride = Hh; }
        else        { hsrc = g_out + ((size_t)bb * Tt + (t - 1)) * Hh; bstride = (size_t)Tt * Hh; }

        // prefetch xin for both phases (latency hidden under stage+compute)
        const size_t gi0 = (orow0 + t) * Hh + jb + jo;
        const size_t gi1 = (orow1 + t) * Hh + jb + jo;
        const float xpre0 = g_xin[gi0];
        const float xpre1 = g_xin[gi1];

#pragma unroll
        for (int it = 0; it < 32; it++) {
            const int fid = it * 256 + tid;
            const int b  = fid >> 9;
            const int P  = fid & 511;
            unsigned long long v =
                *(const unsigned long long*)(hsrc + (size_t)b * bstride + P * 2);
            Hs[b * 544 + (P & 15) * 33 + (P >> 4)] = v;
        }
        __syncthreads();

#pragma unroll
        for (int ph = 0; ph < 2; ph++) {
            float* Rs = (ph == 0) ? Rs0 : Rs1;

            unsigned long long acc[8][4];
#pragma unroll
            for (int i = 0; i < 8; i++)
#pragma unroll
                for (int j = 0; j < 4; j++) acc[i][j] = 0ULL;

#pragma unroll
            for (int b8 = 0; b8 < 8; b8++) {
                const unsigned long long* hrow = Hs + (ph * 8 + b8) * 544 + kc;
#pragma unroll
                for (int p = 0; p < 16; p++) {
                    const unsigned long long h2 = hrow[p * 33];
                    FFMA2(acc[b8][0], h2, w[0][p], acc[b8][0]);
                    FFMA2(acc[b8][1], h2, w[1][p], acc[b8][1]);
                    FFMA2(acc[b8][2], h2, w[2][p], acc[b8][2]);
                    FFMA2(acc[b8][3], h2, w[3][p], acc[b8][3]);
                }
            }

            // write k-partials (no pre-sync needed: prior-step reads were
            // ordered by the step-ending grid barrier / ph0 by this step's
            // own double buffer)
#pragma unroll
            for (int b8 = 0; b8 < 8; b8++)
#pragma unroll
                for (int jj = 0; jj < 4; jj++) {
                    float2 pa = *(float2*)&acc[b8][jj];
                    const int o = b8 * 32 + jg * 4 + jj;
                    Rs[o * 33 + kc] = pa.x + pa.y;
                }
            __syncthreads();

            {
                const float* rp = Rs + tid * 33;
                float s0 = 0.f, s1 = 0.f, s2 = 0.f, s3 = 0.f;
#pragma unroll
                for (int i = 0; i < 32; i += 4) {
                    s0 += rp[i + 0]; s1 += rp[i + 1];
                    s2 += rp[i + 2]; s3 += rp[i + 3];
                }
                const float sum = (s0 + s1) + (s2 + s3);

                const size_t base_i = (ph == 0) ? gi0 : gi1;
                const float xin = (ph == 0) ? xpre0 : xpre1;
                const float v = fmaxf(sum + xin, 0.f);
                g_out[base_i] = v;

                uint16_t hv; CVT_BF16(hv, v);
                const float rres = v - __uint_as_float((uint32_t)hv << 16);
                uint16_t lv; CVT_BF16(lv, rres);
                g_oh[base_i] = hv;
                g_ol[base_i] = lv;

                if (t == Tt - 1)
                    hn[(size_t)(bb + ph * 8 + bl0) * Hh + jb + jo] = v;
            }
        }

        group_barrier(grp);
    }
}

// ---------------------------------------------------------------------------
extern "C" void kernel_launch(void* const* d_in, const int* in_sizes, int n_in,
                              void* d_out, int out_size)
{
    const float* x      = (const float*)d_in[0];
    const float* hidden = (const float*)d_in[1];
    const float* Wih0   = (const float*)d_in[2];
    const float* Whh0   = (const float*)d_in[3];
    const float* bih0   = (const float*)d_in[4];
    const float* bhh0   = (const float*)d_in[5];
    const float* WihL   = (const float*)d_in[6];
    const float* WhhL   = (const float*)d_in[7];
    const float* bihL   = (const float*)d_in[8];
    const float* bhhL   = (const float*)d_in[9];
    const float* Wfc    = (const float*)d_in[10];
    const float* bfc    = (const float*)d_in[11];
    float* out = (float*)d_out;

    float* xin_p = nullptr;
    uint16_t *xh_p, *xl_p, *oh_p, *ol_p, *wh_p, *wl_p;
    cudaGetSymbolAddress((void**)&xin_p, g_xin);
    cudaGetSymbolAddress((void**)&xh_p, g_xh);
    cudaGetSymbolAddress((void**)&xl_p, g_xl);
    cudaGetSymbolAddress((void**)&oh_p, g_oh);
    cudaGetSymbolAddress((void**)&ol_p, g_ol);
    cudaGetSymbolAddress((void**)&wh_p, g_wh);
    cudaGetSymbolAddress((void**)&wl_p, g_wl);

    cudaFuncSetAttribute(rnn_scan_kernel,
                         cudaFuncAttributeMaxDynamicSharedMemorySize, SCAN_SMEM);
    cudaFuncSetAttribute(gemm_bias_kernel,
                         cudaFuncAttributeMaxDynamicSharedMemorySize, GEMM_SMEM);

    // prep: split x and GEMM weights into bf16 hi/lo (Whh stays f32 for scan)
    cvt_hilo_kernel<<<(Bb * Tt * Ii + 255) / 256, 256>>>(
        x, xh_p, xl_p, Bb * Tt * Ii);
    cvt_hilo_kernel<<<(Hh * Ii + 255) / 256, 256>>>(
        Wih0, wh_p + W_OFF_IH0, wl_p + W_OFF_IH0, Hh * Ii);
    cvt_hilo_kernel<<<((Ll - 1) * Hh * Hh + 255) / 256, 256>>>(
        WihL, wh_p + W_OFF_IHL, wl_p + W_OFF_IHL, (Ll - 1) * Hh * Hh);
    cvt_hilo_kernel<<<(Oo * Hh + 255) / 256, 256>>>(
        Wfc, wh_p + W_OFF_FC, wl_p + W_OFF_FC, Oo * Hh);

    const dim3 projGrid(Mm / 128, Hh / 128);   // 256 x 8
    const dim3 scanGrid(Hh / 32, NGROUP);      // 32 x 4 = 128 CTAs (1/SM)
    float* hn_base = out + (size_t)Bb * Tt * Oo;

    for (int l = 0; l < Ll; l++) {
        const float *Whh, *bi, *bh;
        if (l == 0) { Whh = Whh0; bi = bih0; bh = bhh0; }
        else {
            Whh = WhhL + (size_t)(l - 1) * Hh * Hh;
            bi  = bihL + (size_t)(l - 1) * Hh;
            bh  = bhhL + (size_t)(l - 1) * Hh;
        }

        // time-parallel input projection: g_xin = in @ Wih^T + b_ih + b_hh
        if (l == 0)
            gemm_bias_kernel<<<projGrid, 256, GEMM_SMEM>>>(
                xh_p, xl_p, wh_p + W_OFF_IH0, wl_p + W_OFF_IH0,
                bi, bh, xin_p, Mm, Hh, Ii);
        else
            gemm_bias_kernel<<<projGrid, 256, GEMM_SMEM>>>(
                oh_p, ol_p,
                wh_p + W_OFF_IHL + (size_t)(l - 1) * Hh * Hh,
                wl_p + W_OFF_IHL + (size_t)(l - 1) * Hh * Hh,
                bi, bh, xin_p, Mm, Hh, Hh);

        // persistent FFMA2 scan: all 512 steps in one launch
        rnn_scan_kernel<<<scanGrid, 256, SCAN_SMEM>>>(
            Whh, hidden + (size_t)l * Bb * Hh, hn_base + (size_t)l * Bb * Hh);
    }

    // output projection: out = h_last @ W_fc^T + b_fc
    gemm_bias_kernel<<<dim3(Mm / 128, Oo / 128), 256, GEMM_SMEM>>>(
        oh_p, ol_p, wh_p + W_OFF_FC, wl_p + W_OFF_FC,
        bfc, nullptr, out, Mm, Oo, Hh);
}

// round 17
// speedup vs baseline: 2.4984x; 1.4662x over previous
#include <cuda_runtime.h>
#include <cstdint>

#define Bb 64
#define Tt 512
#define Ii 128
#define Hh 1024
#define Ll 4
#define Oo 128
#define Mm (Bb * Tt)   // 32768

#define NGROUP 4       // independent batch-groups (16 b-rows each)
#define GRP_NBLK 32    // CTAs per group barrier (the j-tiles)

// packed fp32 pair FMA
#define FFMA2(d, a, b, c) \
    asm("fma.rn.f32x2 %0, %1, %2, %3;" : "=l"(d) : "l"(a), "l"(b), "l"(c))

// bf16 tensor-core mma: D(4xf32) += A(4x.b32 bf16x2) * B(2x.b32 bf16x2)
#define MMA_BF16(c, a, b) \
    asm("mma.sync.aligned.m16n8k16.row.col.f32.bf16.bf16.f32 " \
        "{%0,%1,%2,%3}, {%4,%5,%6,%7}, {%8,%9}, {%0,%1,%2,%3};" \
        : "+f"((c)[0]), "+f"((c)[1]), "+f"((c)[2]), "+f"((c)[3]) \
        : "r"((a)[0]), "r"((a)[1]), "r"((a)[2]), "r"((a)[3]), \
          "r"((b)[0]), "r"((b)[1]))

#define LDSM_X4(r, addr) \
    asm("ldmatrix.sync.aligned.m8n8.x4.shared.b16 {%0,%1,%2,%3}, [%4];" \
        : "=r"((r)[0]), "=r"((r)[1]), "=r"((r)[2]), "=r"((r)[3]) \
        : "r"(addr))

#define CVT_BF16(h, v) \
    asm("cvt.rn.bf16.f32 %0, %1;" : "=h"(h) : "f"(v))

// fp32 scratch
__device__ float g_xin[(size_t)Bb * Tt * Hh];
__device__ float g_out[(size_t)Bb * Tt * Hh];

// bf16 hi/lo planes (pre-split GEMM operands)
__device__ uint16_t g_xh[(size_t)Bb * Tt * Ii];   // input x
__device__ uint16_t g_xl[(size_t)Bb * Tt * Ii];
__device__ uint16_t g_oh[(size_t)Bb * Tt * Hh];   // layer output (scan-written)
__device__ uint16_t g_ol[(size_t)Bb * Tt * Hh];

#define W_OFF_IH0 0
#define W_OFF_IHL (Hh * Ii)
#define W_OFF_FC  (W_OFF_IHL + (Ll - 1) * Hh * Hh)
#define W_TOTAL   (W_OFF_FC + Oo * Hh)
__device__ uint16_t g_wh[W_TOTAL];
__device__ uint16_t g_wl[W_TOTAL];

// Per-group software barrier — R12-proven form: single atomic counter +
// single volatile phase word per group. Monotonic phase compared against a
// locally captured snapshot -> replay-safe. Spin bounded by clock64.
__device__ unsigned g_bar_count[NGROUP];
__device__ volatile unsigned g_bar_phase[NGROUP];

__device__ __forceinline__ void group_barrier(int g)
{
    __threadfence();
    __syncthreads();
    if (threadIdx.x == 0) {
        const unsigned old = g_bar_phase[g];
        if (atomicAdd(&g_bar_count[g], 1u) == GRP_NBLK - 1) {
            g_bar_count[g] = 0;
            __threadfence();
            g_bar_phase[g] = old + 1;
        } else {
            const long long t0 = clock64();
            while (g_bar_phase[g] == old) {
                if (clock64() - t0 > 40000000LL) break;   // escape hatch
            }
        }
        __threadfence();
    }
    __syncthreads();
}

// ---------------------------------------------------------------------------
// f32 -> (hi, lo) bf16 split prep
// ---------------------------------------------------------------------------
__global__ void cvt_hilo_kernel(const float* __restrict__ src,
                                uint16_t* __restrict__ hi,
                                uint16_t* __restrict__ lo, int n)
{
    const int i = blockIdx.x * blockDim.x + threadIdx.x;
    if (i < n) {
        const float v = src[i];
        uint16_t h; CVT_BF16(h, v);
        const float r = v - __uint_as_float((uint32_t)h << 16);
        uint16_t l; CVT_BF16(l, r);
        hi[i] = h; lo[i] = l;
    }
}

// ---------------------------------------------------------------------------
// Tensor-core GEMM on pre-split bf16 hi/lo operands (3-term, ~2^-16).
// (verbatim R12-passing kernel: 256 thr, 128x128 tile, BK32, double-buffered)
// ---------------------------------------------------------------------------
#define GSTRIDE 40
#define GTILE_B (128 * GSTRIDE * 2)
#define GAH_OFF 0
#define GAL_OFF (2 * GTILE_B)
#define GWH_OFF (4 * GTILE_B)
#define GWL_OFF (6 * GTILE_B)
#define GEMM_SMEM (8 * GTILE_B)

__global__ __launch_bounds__(256, 1) void gemm_bias_kernel(
    const uint16_t* __restrict__ Ah, const uint16_t* __restrict__ Al,
    const uint16_t* __restrict__ Wh, const uint16_t* __restrict__ Wl,
    const float* __restrict__ b1, const float* __restrict__ b2,
    float* __restrict__ C, int M, int N, int K)
{
    extern __shared__ __align__(16) char gsm[];
    uint16_t* sm16 = (uint16_t*)gsm;
    const uint32_t sbase = (uint32_t)__cvta_generic_to_shared(gsm);

    const int bm = blockIdx.x * 128;
    const int bn = blockIdx.y * 128;
    const int tid = threadIdx.x;
    const int wid = tid >> 5;
    const int lane = tid & 31;
    const int warpM = (wid >> 2) * 64;
    const int warpN = (wid & 3) * 32;
    const int lrowA = lane & 15;
    const int lcol8 = (lane >> 4) * 8;
    const int bnrow = lane >> 2;
    const int bk2   = (lane & 3) * 2;

    const int lrow  = tid >> 1;
    const int lhalf = tid & 1;
    const uint16_t* aph = Ah + (size_t)(bm + lrow) * K + lhalf * 16;
    const uint16_t* apl = Al + (size_t)(bm + lrow) * K + lhalf * 16;
    const uint16_t* wph = Wh + (size_t)(bn + lrow) * K + lhalf * 16;
    const uint16_t* wpl = Wl + (size_t)(bn + lrow) * K + lhalf * 16;
    const int sidx = lrow * GSTRIDE + lhalf * 16;

    float c[4][4][4];
#pragma unroll
    for (int mt = 0; mt < 4; mt++)
#pragma unroll
        for (int nt = 0; nt < 4; nt++)
#pragma unroll
            for (int i = 0; i < 4; i++) c[mt][nt][i] = 0.f;

    uint4 rah[2], ral[2], rwh[2], rwl[2];
#pragma unroll
    for (int q = 0; q < 2; q++) {
        rah[q] = *(const uint4*)(aph + q * 8);
        ral[q] = *(const uint4*)(apl + q * 8);
        rwh[q] = *(const uint4*)(wph + q * 8);
        rwl[q] = *(const uint4*)(wpl + q * 8);
    }
#pragma unroll
    for (int q = 0; q < 2; q++) {
        *(uint4*)&sm16[(GAH_OFF >> 1) + sidx + q * 8] = rah[q];
        *(uint4*)&sm16[(GAL_OFF >> 1) + sidx + q * 8] = ral[q];
        *(uint4*)&sm16[(GWH_OFF >> 1) + sidx + q * 8] = rwh[q];
        *(uint4*)&sm16[(GWL_OFF >> 1) + sidx + q * 8] = rwl[q];
    }
    __syncthreads();

    const int nkb = K / 32;
    int cur = 0;
    for (int kb = 0; kb < nkb; kb++) {
        if (kb + 1 < nkb) {
            const int k = (kb + 1) * 32;
#pragma unroll
            for (int q = 0; q < 2; q++) {
                rah[q] = *(const uint4*)(aph + k + q * 8);
                ral[q] = *(const uint4*)(apl + k + q * 8);
                rwh[q] = *(const uint4*)(wph + k + q * 8);
                rwl[q] = *(const uint4*)(wpl + k + q * 8);
            }
        }

        const uint32_t ah_b = sbase + GAH_OFF + cur * GTILE_B;
        const uint32_t al_b = sbase + GAL_OFF + cur * GTILE_B;
        const int wh_e = ((GWH_OFF + cur * GTILE_B) >> 1);
        const int wl_e = ((GWL_OFF + cur * GTILE_B) >> 1);

#pragma unroll
        for (int k16 = 0; k16 < 2; k16++) {
            const int koff = k16 * 16;
            uint32_t ah[4][4], al[4][4];
#pragma unroll
            for (int mt = 0; mt < 4; mt++) {
                const uint32_t ro =
                    ((warpM + mt * 16 + lrowA) * GSTRIDE + koff + lcol8) * 2;
                LDSM_X4(ah[mt], ah_b + ro);
                LDSM_X4(al[mt], al_b + ro);
            }
            uint32_t bh[4][2], bl[4][2];
#pragma unroll
            for (int nt = 0; nt < 4; nt++) {
                const int idx =
                    (warpN + nt * 8 + bnrow) * GSTRIDE + koff + bk2;
                bh[nt][0] = *(const uint32_t*)&sm16[wh_e + idx];
                bh[nt][1] = *(const uint32_t*)&sm16[wh_e + idx + 8];
                bl[nt][0] = *(const uint32_t*)&sm16[wl_e + idx];
                bl[nt][1] = *(const uint32_t*)&sm16[wl_e + idx + 8];
            }
#pragma unroll
            for (int mt = 0; mt < 4; mt++)
#pragma unroll
                for (int nt = 0; nt < 4; nt++) {
                    MMA_BF16(c[mt][nt], ah[mt], bh[nt]);
                    MMA_BF16(c[mt][nt], ah[mt], bl[nt]);
                    MMA_BF16(c[mt][nt], al[mt], bh[nt]);
                }
        }

        if (kb + 1 < nkb) {
            const int nxt = cur ^ 1;
            const int ah_e = ((GAH_OFF + nxt * GTILE_B) >> 1);
            const int al_e = ((GAL_OFF + nxt * GTILE_B) >> 1);
            const int wh_e2 = ((GWH_OFF + nxt * GTILE_B) >> 1);
            const int wl_e2 = ((GWL_OFF + nxt * GTILE_B) >> 1);
#pragma unroll
            for (int q = 0; q < 2; q++) {
                *(uint4*)&sm16[ah_e + sidx + q * 8] = rah[q];
                *(uint4*)&sm16[al_e + sidx + q * 8] = ral[q];
                *(uint4*)&sm16[wh_e2 + sidx + q * 8] = rwh[q];
                *(uint4*)&sm16[wl_e2 + sidx + q * 8] = rwl[q];
            }
            __syncthreads();
            cur = nxt;
        }
    }

#pragma unroll
    for (int nt = 0; nt < 4; nt++) {
        const int col = bn + warpN + nt * 8 + bk2;
        float bx = b1[col], by = b1[col + 1];
        if (b2 != nullptr) { bx += b2[col]; by += b2[col + 1]; }
#pragma unroll
        for (int mt = 0; mt < 4; mt++) {
            const int row = bm + warpM + mt * 16 + (lane >> 2);
            float2 s0 = make_float2(c[mt][nt][0] + bx, c[mt][nt][1] + by);
            float2 s1 = make_float2(c[mt][nt][2] + bx, c[mt][nt][3] + by);
            *(float2*)&C[(size_t)row * N + col] = s0;
            *(float2*)&C[(size_t)(row + 8) * N + col] = s1;
        }
    }
}

// ---------------------------------------------------------------------------
// Persistent FFMA2 scan, W-IN-REGISTERS + bf16 hi/lo emission.
//   g_out[b,t,j] = relu(g_xin[b,t,j] + sum_k h_prev[b,k] * Whh[j,k])
// EXACT R12 structure (single Rs, all 7 syncs, atomic barrier). One change:
// xin is staged through a 2KB smem buffer (Xs) during the h-staging loop
// (coalesced LDGs amortized with staging traffic) and read back via LDS in
// the reduce — removing the exposed ~600-cyc LDG from each phase's tail.
// Register-neutral: no step-long-lived registers added.
// ---------------------------------------------------------------------------
#define HS_WORDS (16 * 544)                        // 8B words (69632 B)
#define RS_FLOATS (256 * 33)                       // 33792 B
#define XS_OFF (HS_WORDS * 8 + RS_FLOATS * 4)      // 103424
#define SCAN_SMEM (XS_OFF + 512 * 4)               // 105472 B

__global__ __launch_bounds__(256, 1) void rnn_scan_kernel(
    const float* __restrict__ Whh, const float* __restrict__ hid,
    float* __restrict__ hn)
{
    extern __shared__ __align__(16) char smraw[];
    unsigned long long* Hs = (unsigned long long*)smraw;
    float* Rs = (float*)(smraw + HS_WORDS * 8);
    float* Xs = (float*)(smraw + XS_OFF);          // [2][256] xin staging

    const int jb  = blockIdx.x * 32;
    const int grp = blockIdx.y;
    const int bb  = grp * 16;
    const int tid = threadIdx.x;
    const int jg  = tid >> 5;
    const int kc  = tid & 31;

    unsigned long long w[4][16];
#pragma unroll
    for (int jj = 0; jj < 4; jj++) {
        const float* wr = Whh + (size_t)(jb + jg * 4 + jj) * Hh + kc * 32;
#pragma unroll
        for (int p = 0; p < 16; p++)
            w[jj][p] = *(const unsigned long long*)(wr + p * 2);
    }

    for (int t = 0; t < Tt; t++) {
        const float* hsrc;
        size_t bstride;
        if (t == 0) { hsrc = hid + (size_t)bb * Hh;                    bstride = Hh; }
        else        { hsrc = g_out + ((size_t)bb * Tt + (t - 1)) * Hh; bstride = (size_t)Tt * Hh; }

#pragma unroll
        for (int it = 0; it < 32; it++) {
            const int fid = it * 256 + tid;
            const int b  = fid >> 9;
            const int P  = fid & 511;
            unsigned long long v =
                *(const unsigned long long*)(hsrc + (size_t)b * bstride + P * 2);
            Hs[b * 544 + (P & 15) * 33 + (P >> 4)] = v;
        }
        // stage this step's xin (2 coalesced LDGs, hidden among staging LDGs)
        {
            const int bl = tid >> 5;
            const int j  = tid & 31;
            Xs[tid]       = g_xin[((size_t)(bb + bl) * Tt + t) * Hh + jb + j];
            Xs[256 + tid] = g_xin[((size_t)(bb + 8 + bl) * Tt + t) * Hh + jb + j];
        }
        __syncthreads();

#pragma unroll
        for (int ph = 0; ph < 2; ph++) {
            unsigned long long acc[8][4];
#pragma unroll
            for (int i = 0; i < 8; i++)
#pragma unroll
                for (int j = 0; j < 4; j++) acc[i][j] = 0ULL;

#pragma unroll
            for (int b8 = 0; b8 < 8; b8++) {
                const unsigned long long* hrow = Hs + (ph * 8 + b8) * 544 + kc;
#pragma unroll
                for (int p = 0; p < 16; p++) {
                    const unsigned long long h2 = hrow[p * 33];
                    FFMA2(acc[b8][0], h2, w[0][p], acc[b8][0]);
                    FFMA2(acc[b8][1], h2, w[1][p], acc[b8][1]);
                    FFMA2(acc[b8][2], h2, w[2][p], acc[b8][2]);
                    FFMA2(acc[b8][3], h2, w[3][p], acc[b8][3]);
                }
            }

            __syncthreads();   // ph=1: previous reduce-read must finish
#pragma unroll
            for (int b8 = 0; b8 < 8; b8++)
#pragma unroll
                for (int jj = 0; jj < 4; jj++) {
                    float2 pa = *(float2*)&acc[b8][jj];
                    const int o = b8 * 32 + jg * 4 + jj;
                    Rs[o * 33 + kc] = pa.x + pa.y;
                }
            __syncthreads();

            {
                const int o  = tid;
                const int bl = o >> 5;
                const int j  = o & 31;
                const float* rp = Rs + o * 33;
                float s0 = 0.f, s1 = 0.f, s2 = 0.f, s3 = 0.f;
#pragma unroll
                for (int i = 0; i < 32; i += 4) {
                    s0 += rp[i + 0]; s1 += rp[i + 1];
                    s2 += rp[i + 2]; s3 += rp[i + 3];
                }
                const float sum = (s0 + s1) + (s2 + s3);

                const int bg = bb + ph * 8 + bl;
                const int jgl = jb + j;
                const size_t base = ((size_t)bg * Tt + t) * Hh + jgl;
                const float v = fmaxf(sum + Xs[ph * 256 + tid], 0.f);
                g_out[base] = v;

                uint16_t hv; CVT_BF16(hv, v);
                const float rres = v - __uint_as_float((uint32_t)hv << 16);
                uint16_t lv; CVT_BF16(lv, rres);
                g_oh[base] = hv;
                g_ol[base] = lv;

                if (t == Tt - 1)
                    hn[(size_t)bg * Hh + jgl] = v;
            }
        }

        group_barrier(grp);
    }
}

// ---------------------------------------------------------------------------
extern "C" void kernel_launch(void* const* d_in, const int* in_sizes, int n_in,
                              void* d_out, int out_size)
{
    const float* x      = (const float*)d_in[0];
    const float* hidden = (const float*)d_in[1];
    const float* Wih0   = (const float*)d_in[2];
    const float* Whh0   = (const float*)d_in[3];
    const float* bih0   = (const float*)d_in[4];
    const float* bhh0   = (const float*)d_in[5];
    const float* WihL   = (const float*)d_in[6];
    const float* WhhL   = (const float*)d_in[7];
    const float* bihL   = (const float*)d_in[8];
    const float* bhhL   = (const float*)d_in[9];
    const float* Wfc    = (const float*)d_in[10];
    const float* bfc    = (const float*)d_in[11];
    float* out = (float*)d_out;

    float* xin_p = nullptr;
    uint16_t *xh_p, *xl_p, *oh_p, *ol_p, *wh_p, *wl_p;
    cudaGetSymbolAddress((void**)&xin_p, g_xin);
    cudaGetSymbolAddress((void**)&xh_p, g_xh);
    cudaGetSymbolAddress((void**)&xl_p, g_xl);
    cudaGetSymbolAddress((void**)&oh_p, g_oh);
    cudaGetSymbolAddress((void**)&ol_p, g_ol);
    cudaGetSymbolAddress((void**)&wh_p, g_wh);
    cudaGetSymbolAddress((void**)&wl_p, g_wl);

    cudaFuncSetAttribute(rnn_scan_kernel,
                         cudaFuncAttributeMaxDynamicSharedMemorySize, SCAN_SMEM);
    cudaFuncSetAttribute(gemm_bias_kernel,
                         cudaFuncAttributeMaxDynamicSharedMemorySize, GEMM_SMEM);

    // prep: split x and GEMM weights into bf16 hi/lo (Whh stays f32 for scan)
    cvt_hilo_kernel<<<(Bb * Tt * Ii + 255) / 256, 256>>>(
        x, xh_p, xl_p, Bb * Tt * Ii);
    cvt_hilo_kernel<<<(Hh * Ii + 255) / 256, 256>>>(
        Wih0, wh_p + W_OFF_IH0, wl_p + W_OFF_IH0, Hh * Ii);
    cvt_hilo_kernel<<<((Ll - 1) * Hh * Hh + 255) / 256, 256>>>(
        WihL, wh_p + W_OFF_IHL, wl_p + W_OFF_IHL, (Ll - 1) * Hh * Hh);
    cvt_hilo_kernel<<<(Oo * Hh + 255) / 256, 256>>>(
        Wfc, wh_p + W_OFF_FC, wl_p + W_OFF_FC, Oo * Hh);

    const dim3 projGrid(Mm / 128, Hh / 128);   // 256 x 8
    const dim3 scanGrid(Hh / 32, NGROUP);      // 32 x 4 = 128 CTAs (1/SM)
    float* hn_base = out + (size_t)Bb * Tt * Oo;

    for (int l = 0; l < Ll; l++) {
        const float *Whh, *bi, *bh;
        if (l == 0) { Whh = Whh0; bi = bih0; bh = bhh0; }
        else {
            Whh = WhhL + (size_t)(l - 1) * Hh * Hh;
            bi  = bihL + (size_t)(l - 1) * Hh;
            bh  = bhhL + (size_t)(l - 1) * Hh;
        }

        // time-parallel input projection: g_xin = in @ Wih^T + b_ih + b_hh
        if (l == 0)
            gemm_bias_kernel<<<projGrid, 256, GEMM_SMEM>>>(
                xh_p, xl_p, wh_p + W_OFF_IH0, wl_p + W_OFF_IH0,
                bi, bh, xin_p, Mm, Hh, Ii);
        else
            gemm_bias_kernel<<<projGrid, 256, GEMM_SMEM>>>(
                oh_p, ol_p,
                wh_p + W_OFF_IHL + (size_t)(l - 1) * Hh * Hh,
                wl_p + W_OFF_IHL + (size_t)(l - 1) * Hh * Hh,
                bi, bh, xin_p, Mm, Hh, Hh);

        // persistent FFMA2 scan: all 512 steps in one launch
        rnn_scan_kernel<<<scanGrid, 256, SCAN_SMEM>>>(
            Whh, hidden + (size_t)l * Bb * Hh, hn_base + (size_t)l * Bb * Hh);
    }

    // output projection: out = h_last @ W_fc^T + b_fc
    gemm_bias_kernel<<<dim3(Mm / 128, Oo / 128), 256, GEMM_SMEM>>>(
        oh_p, ol_p, wh_p + W_OFF_FC, wl_p + W_OFF_FC,
        bfc, nullptr, out, Mm, Oo, Hh);
}